// round 13
// baseline (speedup 1.0000x reference)
#include <cuda_runtime.h>
#include <cstdint>

// Biquad DF2T, B=512 channels, T=48000, fp32.
// s[n] = M s[n-1] + g x[n],  M = [[-a1,1],[-a2,0]] per-channel constant.
//
// 4 segments/channel (2048 blocks). Each segment processed as 3 tiles of
// 4000 samples, double-buffered in smem via cp.async (tile k+2 prefetch
// overlaps tile k/k+1 compute). Per tile: 500 chunks x 8 samples, one chunk
// per thread; y0 kept in REGISTERS (no smem round-trip).
//   passA : zero-state recurrence from smem x -> y0[8] regs + end state
//   scan  : shuffle two-level affine scan, seeded at thread 0 (Q = M^8)
//   store : in-register correction y0[j] += row0(M^j).s  then 2x STG.128
// Tile carry via one smem float2; segment chain via device globals
// (thread 0 spins at tile 0, thread 499 publishes at tile 2). 4 CTAs/SM.

#define NCHAN   512
#define TLEN    48000
#define NSEG    4
#define SEG     12000
#define NTILE   3
#define TILE    4000
#define CHUNK   8
#define NCHT    500         // chunks per tile
#define RSTRIDE 9           // row stride in floats (8 + 1 pad, odd)
#define THREADS 512
#define NBLK    (NCHAN * NSEG)
#define BUF_FLOATS (NCHT * RSTRIDE)   // 4500

struct SmemLayout {
    float  buf[2][BUF_FLOATS];   // x tiles (padded: addr = 9*chunk + j)
    float4 gt[32];               // Q^(lane+1)
    float2 warp_agg[16];
    float2 warp_E[16];
    float2 carry;                // true state at end of current tile
};
#define SMEM_BYTES ((int)sizeof(SmemLayout))

__device__ int    g_flag[NBLK];
__device__ float2 g_state[NBLK];

__global__ void init_flags_kernel() {
    int i = blockIdx.x * blockDim.x + threadIdx.x;
    if (i < NBLK) g_flag[i] = 0;
}

#define MATSQ(p00,p01,p10,p11) do {                                  \
    float _t00 = fmaf(p00, p00, p01 * p10);                          \
    float _t01 = p01 * (p00 + p11);                                  \
    float _t10 = p10 * (p00 + p11);                                  \
    float _t11 = fmaf(p11, p11, p01 * p10);                          \
    p00 = _t00; p01 = _t01; p10 = _t10; p11 = _t11; } while (0)

#define MATMUL_L(e00,e01,e10,e11, m00,m01,m10,m11) do {              \
    float _r00 = fmaf(e00, m00, e01 * m10);                          \
    float _r01 = fmaf(e00, m01, e01 * m11);                          \
    float _r10 = fmaf(e10, m00, e11 * m10);                          \
    float _r11 = fmaf(e10, m01, e11 * m11);                          \
    m00 = _r00; m01 = _r01; m10 = _r10; m11 = _r11; } while (0)

__device__ __forceinline__ void cp_async4(uint32_t dst, const float* src) {
    asm volatile("cp.async.ca.shared.global [%0], [%1], 4;\n"
                 :: "r"(dst), "l"(src));
}
#define CP_COMMIT() asm volatile("cp.async.commit_group;\n" ::: "memory")
#define CP_WAIT(n)  asm volatile("cp.async.wait_group %0;\n" :: "n"(n) : "memory")

// Issue one tile's async copies (all threads), padded layout, then commit.
__device__ __forceinline__ void issue_tile(uint32_t buf_addr,
                                           const float* __restrict__ src,
                                           int tid) {
    #pragma unroll 4
    for (int i = tid; i < TILE; i += THREADS) {
        uint32_t dst = buf_addr + 4u * (RSTRIDE * (i >> 3) + (i & 7));
        cp_async4(dst, src + i);
    }
    CP_COMMIT();
}

__global__ __launch_bounds__(THREADS, 4)
void biquad_kernel(const float* __restrict__ x,
                   const float* __restrict__ gb0,
                   const float* __restrict__ gb1,
                   const float* __restrict__ gb2,
                   const float* __restrict__ ga1,
                   const float* __restrict__ ga2,
                   float* __restrict__ out)
{
    extern __shared__ char smem_raw[];
    SmemLayout* S = (SmemLayout*)smem_raw;

    const int bid  = blockIdx.x;
    const int c    = bid >> 2;
    const int seg  = bid & 3;
    const int tid  = threadIdx.x;
    const int lane = tid & 31;
    const int warp = tid >> 5;

    const uint32_t buf0 = (uint32_t)__cvta_generic_to_shared(S->buf[0]);
    const uint32_t buf1 = (uint32_t)__cvta_generic_to_shared(S->buf[1]);

    const float* xs   = x   + (size_t)c * TLEN + (size_t)seg * SEG;
    float*       outp = out + (size_t)c * TLEN + (size_t)seg * SEG;

    // prologue prefetch: tiles 0,1 (groups g0, g1)
    issue_tile(buf0, xs,        tid);
    issue_tile(buf1, xs + TILE, tid);

    const float A1 = ga1[c], A2 = ga2[c];

    // Q = M^8 : M^2 then 2 squarings
    float q00 = fmaf(A1, A1, -A2), q01 = -A1, q10 = A1 * A2, q11 = -A2;
    MATSQ(q00,q01,q10,q11);
    MATSQ(q00,q01,q10,q11);          // M^8

    // gt[n-1] = Q^n, n = 1..32 (threads 32..63, overlaps the prefetch)
    if (tid >= 32 && tid < 64) {
        int n = tid - 31;
        float r00 = 1.f, r01 = 0.f, r10 = 0.f, r11 = 1.f;
        float e00 = q00, e01 = q01, e10 = q10, e11 = q11;
        #pragma unroll
        for (int k = 0; k < 6; k++) {
            if ((n >> k) & 1) MATMUL_L(e00,e01,e10,e11, r00,r01,r10,r11);
            MATSQ(e00,e01,e10,e11);
        }
        S->gt[tid - 32] = make_float4(r00, r01, r10, r11);
    }

    const float B0 = gb0[c], B1v = gb1[c], B2v = gb2[c];

    CP_WAIT(1);            // tile 0 arrived (this thread's g0)
    __syncthreads();       // all threads' g0 + gt table visible

    #pragma unroll
    for (int k = 0; k < NTILE; k++) {
        const float* bufk = S->buf[k & 1];

        // ---- passA: zero-state recurrence, y0 kept in registers ----
        float y0[CHUNK];
        float z1 = 0.f, z2 = 0.f;
        if (tid < NCHT) {
            const float* p = bufk + tid * RSTRIDE;
            #pragma unroll
            for (int j = 0; j < CHUNK; j++) {
                float xv = p[j];
                float y  = fmaf(B0, xv, z1);
                float w  = fmaf(B1v, xv, z2);
                z1 = fmaf(-A1, y, w);
                z2 = fmaf(-A2, y, B2v * xv);
                y0[j] = y;
            }
        }

        // ---- seed (thread 0): tile carry, or segment look-back at k=0 ----
        float sinx = 0.f, siny = 0.f;
        if (tid == 0) {
            if (k == 0) {
                if (seg > 0) {
                    volatile int* fp = g_flag + (bid - 1);
                    while (*fp == 0) { }
                    __threadfence();
                    volatile float* sp = (volatile float*)&g_state[bid - 1];
                    sinx = sp[0]; siny = sp[1];
                }
            } else {
                float2 t = S->carry; sinx = t.x; siny = t.y;
            }
            z1 = fmaf(q00, sinx, fmaf(q01, siny, z1));   // d0 += Q * s_in
            z2 = fmaf(q10, sinx, fmaf(q11, siny, z2));
        }

        // ---- in-warp inclusive affine scan (level matrix Q^(2^l)) ----
        float ex = z1, ey = z2;
        float l00 = q00, l01 = q01, l10 = q10, l11 = q11;
        #pragma unroll
        for (int o = 1; o < 32; o <<= 1) {
            float px = __shfl_up_sync(0xffffffffu, ex, o);
            float py = __shfl_up_sync(0xffffffffu, ey, o);
            if (lane >= o) {
                ex = fmaf(l00, px, fmaf(l01, py, ex));
                ey = fmaf(l10, px, fmaf(l11, py, ey));
            }
            MATSQ(l00,l01,l10,l11);      // exits as Q^32
        }
        if (lane == 31) S->warp_agg[warp] = make_float2(ex, ey);
        __syncthreads();                                // B2

        // prefetch tile 2 into buf[0]: safe, all passA(0) reads are done
        if (k == 0) issue_tile(buf0, xs + 2 * TILE, tid);   // group g2

        // ---- cross-warp scan of 16 aggregates by warp 0 ----
        if (warp == 0) {
            float wx = 0.f, wy = 0.f;
            if (lane < 16) { float2 t = S->warp_agg[lane]; wx = t.x; wy = t.y; }
            #pragma unroll
            for (int o = 1; o < 16; o <<= 1) {
                float px = __shfl_up_sync(0xffffffffu, wx, o);
                float py = __shfl_up_sync(0xffffffffu, wy, o);
                if (lane >= o && lane < 16) {
                    wx = fmaf(l00, px, fmaf(l01, py, wx));
                    wy = fmaf(l10, px, fmaf(l11, py, wy));
                }
                MATSQ(l00,l01,l10,l11);
            }
            if (lane < 16) S->warp_E[lane] = make_float2(wx, wy);
        }
        __syncthreads();                                // B3

        // ---- apply: e' = w + Q^(lane+1) * E_{warp-1} ----
        float Ex = 0.f, Ey = 0.f;
        if (warp > 0) {
            float2 t = S->warp_E[warp - 1]; Ex = t.x; Ey = t.y;
            float4 g = S->gt[lane];
            ex = fmaf(g.x, Ex, fmaf(g.y, Ey, ex));
            ey = fmaf(g.z, Ex, fmaf(g.w, Ey, ey));
        }
        float pex = __shfl_up_sync(0xffffffffu, ex, 1);
        float pey = __shfl_up_sync(0xffffffffu, ey, 1);
        if (lane == 0) { pex = Ex; pey = Ey; }
        if (tid == 0)  { pex = sinx; pey = siny; }

        // ---- carry / publish (thread 499 holds true tile-end state) ----
        if (tid == NCHT - 1) {
            if (k < NTILE - 1) {
                S->carry = make_float2(ex, ey);
            } else if (seg < NSEG - 1) {
                volatile float* dp = (volatile float*)&g_state[bid];
                dp[0] = ex; dp[1] = ey;
                __threadfence();
                *((volatile int*)(g_flag + bid)) = 1;
            }
        }

        // ---- in-register correction + direct store (2x STG.128) ----
        if (tid < NCHT) {
            float hx = pex, hy = pey;
            #pragma unroll
            for (int j = 0; j < CHUNK; j++) {
                y0[j] += hx;
                float nx = fmaf(-A1, hx, hy);
                hy = -A2 * hx;
                hx = nx;
            }
            float4* o4 = (float4*)(outp + (size_t)k * TILE + tid * CHUNK);
            o4[0] = make_float4(y0[0], y0[1], y0[2], y0[3]);
            o4[1] = make_float4(y0[4], y0[5], y0[6], y0[7]);
        }

        // ---- drain next tile's prefetch, fence the buffers/carry ----
        if (k == 0) { CP_WAIT(1); }     // tile 1 (g1) arrived
        if (k == 1) { CP_WAIT(0); }     // tile 2 (g2) arrived
        if (k < NTILE - 1) __syncthreads();             // B4 / next B1
    }
}

extern "C" void kernel_launch(void* const* d_in, const int* in_sizes, int n_in,
                              void* d_out, int out_size)
{
    const float* x  = (const float*)d_in[0];
    const float* b0 = (const float*)d_in[1];
    const float* b1 = (const float*)d_in[2];
    const float* b2 = (const float*)d_in[3];
    const float* a1 = (const float*)d_in[4];
    const float* a2 = (const float*)d_in[5];
    float* out = (float*)d_out;

    cudaFuncSetAttribute(biquad_kernel,
                         cudaFuncAttributeMaxDynamicSharedMemorySize,
                         SMEM_BYTES);

    init_flags_kernel<<<NBLK / THREADS, THREADS>>>();
    biquad_kernel<<<NBLK, THREADS, SMEM_BYTES>>>(x, b0, b1, b2, a1, a2, out);
}

// round 15
// speedup vs baseline: 1.5368x; 1.5368x over previous
#include <cuda_runtime.h>

// Biquad DF2T, B=512 channels, T=48000, fp32.
// s[n] = M s[n-1] + g x[n],  M = [[-a1,1],[-a2,0]] per-channel constant.
//
// NO smem data staging. 4 segments/channel (2048 blocks), 500 chunks x 24
// consecutive samples, one chunk per thread (512 threads, 12 idle lanes).
//   passA : 6x LDG.128 of own chunk, zero-state recurrence -> end state only
//   scan  : shuffle two-level affine scan (Q = M^24), seeded at thread 0
//   passB : re-load same 6 float4 (L2-hot), seeded recurrence, 6x STG.128
// Cross-segment chain via device globals (thread 0 spins pre-scan with
// __nanosleep backoff, thread 499 publishes post-apply).
// smem ~1KB, 32 regs -> 4 CTAs/SM.

#define NCHAN   512
#define TLEN    48000
#define NSEG    4
#define SEG     12000
#define CHUNK   24
#define NCH     500
#define NF4     6           // float4 per chunk
#define THREADS 512
#define NBLK    (NCHAN * NSEG)

__device__ int    g_flag[NBLK];
__device__ float2 g_state[NBLK];

__global__ void init_flags_kernel() {
    int i = blockIdx.x * blockDim.x + threadIdx.x;
    if (i < NBLK) g_flag[i] = 0;
}

#define MATSQ(p00,p01,p10,p11) do {                                  \
    float _t00 = fmaf(p00, p00, p01 * p10);                          \
    float _t01 = p01 * (p00 + p11);                                  \
    float _t10 = p10 * (p00 + p11);                                  \
    float _t11 = fmaf(p11, p11, p01 * p10);                          \
    p00 = _t00; p01 = _t01; p10 = _t10; p11 = _t11; } while (0)

#define MATMUL_L(e00,e01,e10,e11, m00,m01,m10,m11) do {              \
    float _r00 = fmaf(e00, m00, e01 * m10);                          \
    float _r01 = fmaf(e00, m01, e01 * m11);                          \
    float _r10 = fmaf(e10, m00, e11 * m10);                          \
    float _r11 = fmaf(e10, m01, e11 * m11);                          \
    m00 = _r00; m01 = _r01; m10 = _r10; m11 = _r11; } while (0)

// one DF2T step; updates (z1,z2), returns y
#define BQ_STEP(xv, z1, z2, y) do {                                  \
    y  = fmaf(B0, (xv), z1);                                         \
    float _w = fmaf(B1v, (xv), z2);                                  \
    z1 = fmaf(-A1, y, _w);                                           \
    z2 = fmaf(-A2, y, B2v * (xv));                                   \
} while (0)

__global__ __launch_bounds__(THREADS, 4)
void biquad_kernel(const float* __restrict__ x,
                   const float* __restrict__ gb0,
                   const float* __restrict__ gb1,
                   const float* __restrict__ gb2,
                   const float* __restrict__ ga1,
                   const float* __restrict__ ga2,
                   float* __restrict__ out)
{
    __shared__ float4 gt[32];        // Q^(lane+1)
    __shared__ float2 warp_agg[16];
    __shared__ float2 warp_E[16];

    const int bid  = blockIdx.x;
    const int c    = bid >> 2;
    const int seg  = bid & 3;
    const int tid  = threadIdx.x;
    const int lane = tid & 31;
    const int warp = tid >> 5;

    const float A1  = ga1[c], A2  = ga2[c];
    const float B0  = gb0[c], B1v = gb1[c], B2v = gb2[c];

    // ---- Q = M^24 : M^2, M^3, then 3 squarings ----
    float a00 = fmaf(A1, A1, -A2), a01 = -A1, a10 = A1 * A2, a11 = -A2;  // M^2
    float q00 = fmaf(a00, -A1, -(a01 * A2)), q01 = a00,
          q10 = fmaf(a10, -A1, -(a11 * A2)), q11 = a10;                  // M^3
    #pragma unroll
    for (int k = 0; k < 3; k++) MATSQ(q00,q01,q10,q11);                  // M^24

    // ---- gt[n-1] = Q^n, n = 1..32 (threads 32..63; visible after B2) ----
    if (tid >= 32 && tid < 64) {
        int n = tid - 31;
        float r00 = 1.f, r01 = 0.f, r10 = 0.f, r11 = 1.f;
        float e00 = q00, e01 = q01, e10 = q10, e11 = q11;
        #pragma unroll
        for (int k = 0; k < 6; k++) {
            if ((n >> k) & 1) MATMUL_L(e00,e01,e10,e11, r00,r01,r10,r11);
            MATSQ(e00,e01,e10,e11);
        }
        gt[tid - 32] = make_float4(r00, r01, r10, r11);
    }

    const float* xs = x + (size_t)c * TLEN + (size_t)seg * SEG;
    const float4* xp = (const float4*)(xs) + tid * NF4;

    // ---- passA: zero-state recurrence over own 24 samples (direct LDG) ----
    float z1 = 0.f, z2 = 0.f;
    if (tid < NCH) {
        #pragma unroll
        for (int b = 0; b < NF4; b++) {
            float4 v = xp[b];
            float y;
            BQ_STEP(v.x, z1, z2, y);
            BQ_STEP(v.y, z1, z2, y);
            BQ_STEP(v.z, z1, z2, y);
            BQ_STEP(v.w, z1, z2, y);
        }
    }

    // ---- thread 0: fetch incoming segment state, seed the scan ----
    float sinx = 0.f, siny = 0.f;
    if (tid == 0 && seg > 0) {
        volatile int* fp = g_flag + (bid - 1);
        while (*fp == 0) { __nanosleep(40); }
        __threadfence();
        volatile float* sp = (volatile float*)&g_state[bid - 1];
        sinx = sp[0]; siny = sp[1];
        z1 = fmaf(q00, sinx, fmaf(q01, siny, z1));   // d0 += Q * s_in
        z2 = fmaf(q10, sinx, fmaf(q11, siny, z2));
    }

    // ---- in-warp inclusive affine scan (level matrix Q^(2^l)) ----
    float ex = z1, ey = z2;
    float l00 = q00, l01 = q01, l10 = q10, l11 = q11;
    #pragma unroll
    for (int o = 1; o < 32; o <<= 1) {
        float px = __shfl_up_sync(0xffffffffu, ex, o);
        float py = __shfl_up_sync(0xffffffffu, ey, o);
        if (lane >= o) {
            ex = fmaf(l00, px, fmaf(l01, py, ex));
            ey = fmaf(l10, px, fmaf(l11, py, ey));
        }
        MATSQ(l00,l01,l10,l11);          // exits as Q^32
    }
    if (lane == 31) warp_agg[warp] = make_float2(ex, ey);
    __syncthreads();                                        // B2

    // ---- cross-warp scan of 16 aggregates by warp 0 (matrix Q^32) ----
    if (warp == 0) {
        float wx = 0.f, wy = 0.f;
        if (lane < 16) { float2 t = warp_agg[lane]; wx = t.x; wy = t.y; }
        #pragma unroll
        for (int o = 1; o < 16; o <<= 1) {
            float px = __shfl_up_sync(0xffffffffu, wx, o);
            float py = __shfl_up_sync(0xffffffffu, wy, o);
            if (lane >= o && lane < 16) {
                wx = fmaf(l00, px, fmaf(l01, py, wx));
                wy = fmaf(l10, px, fmaf(l11, py, wy));
            }
            MATSQ(l00,l01,l10,l11);
        }
        if (lane < 16) warp_E[lane] = make_float2(wx, wy);
    }
    __syncthreads();                                        // B3

    // ---- apply: true end state e' = w + Q^(lane+1) * E_{warp-1} ----
    float Ex = 0.f, Ey = 0.f;
    if (warp > 0) {
        float2 t = warp_E[warp - 1]; Ex = t.x; Ey = t.y;
        float4 g = gt[lane];
        ex = fmaf(g.x, Ex, fmaf(g.y, Ey, ex));
        ey = fmaf(g.z, Ex, fmaf(g.w, Ey, ey));
    }
    // previous chunk's true incoming state
    float pex = __shfl_up_sync(0xffffffffu, ex, 1);
    float pey = __shfl_up_sync(0xffffffffu, ey, 1);
    if (lane == 0) { pex = Ex; pey = Ey; }
    if (tid == 0)  { pex = sinx; pey = siny; }

    // ---- publish outgoing segment state (thread NCH-1 holds it) ----
    if (tid == NCH - 1 && seg < NSEG - 1) {
        volatile float* dp = (volatile float*)&g_state[bid];
        dp[0] = ex; dp[1] = ey;
        __threadfence();
        *((volatile int*)(g_flag + bid)) = 1;
    }

    // ---- passB: re-load (L2-hot), seeded recurrence, direct STG.128 ----
    if (tid < NCH) {
        float s1 = pex, s2 = pey;
        float4* o4 = (float4*)(out + (size_t)c * TLEN + (size_t)seg * SEG)
                     + tid * NF4;
        #pragma unroll
        for (int b = 0; b < NF4; b++) {
            float4 v = xp[b];
            float4 yv;
            BQ_STEP(v.x, s1, s2, yv.x);
            BQ_STEP(v.y, s1, s2, yv.y);
            BQ_STEP(v.z, s1, s2, yv.z);
            BQ_STEP(v.w, s1, s2, yv.w);
            o4[b] = yv;
        }
    }
}

extern "C" void kernel_launch(void* const* d_in, const int* in_sizes, int n_in,
                              void* d_out, int out_size)
{
    const float* x  = (const float*)d_in[0];
    const float* b0 = (const float*)d_in[1];
    const float* b1 = (const float*)d_in[2];
    const float* b2 = (const float*)d_in[3];
    const float* a1 = (const float*)d_in[4];
    const float* a2 = (const float*)d_in[5];
    float* out = (float*)d_out;

    init_flags_kernel<<<NBLK / THREADS, THREADS>>>();
    biquad_kernel<<<NBLK, THREADS>>>(x, b0, b1, b2, a1, a2, out);
}